// round 3
// baseline (speedup 1.0000x reference)
#include <cuda_runtime.h>
#include <math.h>

// ---------------- problem constants ----------------
#define TSQ   512
#define BATCH 64
#define INP   256
#define HID   1024
#define OUTD  256
#define DT_A  0.05f

// output buffer layout (floats): [output_tensor | input_proj | tot_rnnhid | tot_output]
static const size_t O_OUTT = 0;                                  // (512,64,256)
static const size_t O_IP   = (size_t)TSQ * BATCH * OUTD;         // (64,512,1024) at 8388608
static const size_t O_HID  = O_IP  + (size_t)BATCH * TSQ * HID;  // (64,512,1024) at 41943040
static const size_t O_OUT  = O_HID + (size_t)BATCH * TSQ * HID;  // (64,512,256)  at 75497472

// ---------------- device scratch (static: no allocations allowed) ----------------
__device__ float    g_th[(size_t)BATCH * TSQ * HID];  // tanh(h_t) history, [b][t][k]
__device__ unsigned g_bar;                            // grid barrier counter (memset to 0 per launch)

// =====================================================================
// Kernel A: input_proj[b][t][h] = sum_i x[t][b][i] * Win[i][h]
// GEMM M=32768 (r = b*512+t), N=1024, K=256.  BM=128 BN=64 BK=16, 8x4/thread.
// =====================================================================
#define BM 128
#define BN 64
#define BK 16
#define AS_LD 136   // padded, keeps 16B alignment (136*4=544 = 34*16)

__global__ __launch_bounds__(256) void input_proj_kernel(
    const float* __restrict__ x, const float* __restrict__ Win, float* __restrict__ ip)
{
    __shared__ float As[BK * AS_LD];
    __shared__ float Bs[BK * BN];

    const int tid = threadIdx.x;
    const int r0  = blockIdx.y * BM;   // row block over M (b = r0>>9, tile stays in one b)
    const int c0  = blockIdx.x * BN;
    const int b   = r0 >> 9;
    const int t0  = r0 & 511;

    const int arow = tid >> 2;         // 0..63
    const int ac4  = tid & 3;          // k sub-block
    const int brow = tid >> 4;         // 0..15
    const int bc4  = tid & 15;

    const int tx = tid & 15;
    const int ty = tid >> 4;

    float acc[8][4];
#pragma unroll
    for (int i = 0; i < 8; i++)
#pragma unroll
        for (int j = 0; j < 4; j++) acc[i][j] = 0.f;

    for (int k0 = 0; k0 < INP; k0 += BK) {
#pragma unroll
        for (int p = 0; p < 2; p++) {
            const int row = arow + p * 64;
            const float4 v = *(const float4*)&x[((size_t)(t0 + row) * BATCH + b) * INP + k0 + ac4 * 4];
            As[(ac4 * 4 + 0) * AS_LD + row] = v.x;
            As[(ac4 * 4 + 1) * AS_LD + row] = v.y;
            As[(ac4 * 4 + 2) * AS_LD + row] = v.z;
            As[(ac4 * 4 + 3) * AS_LD + row] = v.w;
        }
        *(float4*)&Bs[brow * BN + bc4 * 4] =
            *(const float4*)&Win[(size_t)(k0 + brow) * HID + c0 + bc4 * 4];
        __syncthreads();

#pragma unroll
        for (int k = 0; k < BK; k++) {
            float a[8], bf[4];
            *(float4*)&a[0] = *(const float4*)&As[k * AS_LD + ty * 8];
            *(float4*)&a[4] = *(const float4*)&As[k * AS_LD + ty * 8 + 4];
            *(float4*)&bf[0] = *(const float4*)&Bs[k * BN + tx * 4];
#pragma unroll
            for (int i = 0; i < 8; i++)
#pragma unroll
                for (int j = 0; j < 4; j++)
                    acc[i][j] = fmaf(a[i], bf[j], acc[i][j]);
        }
        __syncthreads();
    }

#pragma unroll
    for (int i = 0; i < 8; i++) {
        const int r = r0 + ty * 8 + i;
        float4 v = make_float4(acc[i][0], acc[i][1], acc[i][2], acc[i][3]);
        *(float4*)&ip[(size_t)r * HID + c0 + tx * 4] = v;
    }
}

// =====================================================================
// Kernel B: persistent recurrent scan.
// Grid (32, 4): blockIdx.x = hidden column tile (32 cols), blockIdx.y = batch tile (16 rows).
// Wr slice [1024][32] lives in smem for all 512 steps. h lives in registers.
// One software grid barrier per step; tanh(h) exchanged via g_th[b][t][k].
// =====================================================================
#define NBLK 128u

__global__ __launch_bounds__(256) void rnn_scan_kernel(
    const float* __restrict__ ip, const float* __restrict__ Wr,
    const float* __restrict__ bias, float* __restrict__ hid)
{
    extern __shared__ float smem[];
    float* w_s  = smem;           // [1024][32] = 32768 floats
    float* th_s = smem + 32768;   // [16][1024] = 16384 floats

    const int tid = threadIdx.x;
    const int c0  = blockIdx.x * 32;
    const int r0  = blockIdx.y * 16;

    // load Wr column slice once: w_s[k][j] = Wr[k][c0+j]
    for (int idx = tid; idx < 1024 * 8; idx += 256) {
        const int k = idx >> 3, j4 = idx & 7;
        *(float4*)&w_s[k * 32 + j4 * 4] = *(const float4*)&Wr[(size_t)k * HID + c0 + j4 * 4];
    }

    const int row = tid >> 4;      // 0..15 (batch row within tile)
    const int jp  = tid & 15;      // column pair index
    const int b   = r0 + row;

    const float2 bia = *(const float2*)&bias[c0 + 2 * jp];
    float h0 = 0.f, h1 = 0.f;
    const float a = DT_A;

    __syncthreads();

    for (int t = 0; t < TSQ; t++) {
        float acc0 = 0.f, acc1 = 0.f;
        if (t > 0) {
            // wait for all CTAs to finish step t-1
            if (tid == 0) {
                while (*(volatile unsigned*)&g_bar < (unsigned)t * NBLK) { }
            }
            __syncthreads();
            __threadfence();

            // stage tanh(h_{t-1}) for our 16 batch rows into smem
            for (int idx = tid; idx < 16 * 256; idx += 256) {
                const int rr = idx >> 8, k4 = idx & 255;
                *(float4*)&th_s[rr * 1024 + k4 * 4] =
                    *(const float4*)&g_th[(size_t)((r0 + rr) * TSQ + (t - 1)) * HID + k4 * 4];
            }
            __syncthreads();

            const float* thr = &th_s[row * 1024];
            const float* wp  = &w_s[2 * jp];
#pragma unroll 8
            for (int k = 0; k < 1024; k++) {
                const float av = thr[k];
                const float2 w = *(const float2*)&wp[k * 32];
                acc0 = fmaf(av, w.x, acc0);
                acc1 = fmaf(av, w.y, acc1);
            }
        }

        const size_t oidx = (size_t)(b * TSQ + t) * HID + c0 + 2 * jp;
        const float2 ipv = *(const float2*)&ip[oidx];
        h0 = (1.f - a) * h0 + a * (acc0 + ipv.x + bia.x);
        h1 = (1.f - a) * h1 + a * (acc1 + ipv.y + bia.y);
        *(float2*)&hid[oidx] = make_float2(h0, h1);

        const float th0 = tanhf(h0), th1 = tanhf(h1);
        *(float2*)&g_th[oidx] = make_float2(th0, th1);

        // release: make stores visible, then arrive
        __threadfence();
        __syncthreads();
        if (tid == 0) atomicAdd(&g_bar, 1u);
    }
}

// =====================================================================
// Kernel C: tot_output = tanh(hid) @ Wout  (tanh already in g_th),
// plus transposed copy output_tensor[t][b][o].
// GEMM M=32768, N=256, K=1024. Same tiling as kernel A.
// =====================================================================
__global__ __launch_bounds__(256) void output_kernel(
    const float* __restrict__ Wout, float* __restrict__ tot_out, float* __restrict__ outT)
{
    __shared__ float As[BK * AS_LD];
    __shared__ float Bs[BK * BN];

    const int tid = threadIdx.x;
    const int r0  = blockIdx.y * BM;
    const int c0  = blockIdx.x * BN;

    const int arow = tid >> 2;
    const int ac4  = tid & 3;
    const int brow = tid >> 4;
    const int bc4  = tid & 15;

    const int tx = tid & 15;
    const int ty = tid >> 4;

    float acc[8][4];
#pragma unroll
    for (int i = 0; i < 8; i++)
#pragma unroll
        for (int j = 0; j < 4; j++) acc[i][j] = 0.f;

    for (int k0 = 0; k0 < HID; k0 += BK) {
#pragma unroll
        for (int p = 0; p < 2; p++) {
            const int row = arow + p * 64;
            const float4 v = *(const float4*)&g_th[(size_t)(r0 + row) * HID + k0 + ac4 * 4];
            As[(ac4 * 4 + 0) * AS_LD + row] = v.x;
            As[(ac4 * 4 + 1) * AS_LD + row] = v.y;
            As[(ac4 * 4 + 2) * AS_LD + row] = v.z;
            As[(ac4 * 4 + 3) * AS_LD + row] = v.w;
        }
        *(float4*)&Bs[brow * BN + bc4 * 4] =
            *(const float4*)&Wout[(size_t)(k0 + brow) * OUTD + c0 + bc4 * 4];
        __syncthreads();

#pragma unroll
        for (int k = 0; k < BK; k++) {
            float a[8], bf[4];
            *(float4*)&a[0] = *(const float4*)&As[k * AS_LD + ty * 8];
            *(float4*)&a[4] = *(const float4*)&As[k * AS_LD + ty * 8 + 4];
            *(float4*)&bf[0] = *(const float4*)&Bs[k * BN + tx * 4];
#pragma unroll
            for (int i = 0; i < 8; i++)
#pragma unroll
                for (int j = 0; j < 4; j++)
                    acc[i][j] = fmaf(a[i], bf[j], acc[i][j]);
        }
        __syncthreads();
    }

#pragma unroll
    for (int i = 0; i < 8; i++) {
        const int r  = r0 + ty * 8 + i;
        const int bb = r >> 9;
        const int tt = r & 511;
        float4 v = make_float4(acc[i][0], acc[i][1], acc[i][2], acc[i][3]);
        *(float4*)&tot_out[(size_t)r * OUTD + c0 + tx * 4] = v;
        *(float4*)&outT[((size_t)tt * BATCH + bb) * OUTD + c0 + tx * 4] = v;
    }
}

// =====================================================================
// launch
// =====================================================================
extern "C" void kernel_launch(void* const* d_in, const int* in_sizes, int n_in,
                              void* d_out, int out_size)
{
    const float* x    = (const float*)d_in[0];
    const float* Win  = (const float*)d_in[1];
    const float* Wr   = (const float*)d_in[2];
    const float* bias = (const float*)d_in[3];
    const float* Wout = (const float*)d_in[4];

    float* out    = (float*)d_out;
    float* o_outT = out + O_OUTT;
    float* o_ip   = out + O_IP;
    float* o_hid  = out + O_HID;
    float* o_out  = out + O_OUT;

    // reset the grid barrier counter (graph-capturable, deterministic replays)
    void* barp = nullptr;
    cudaGetSymbolAddress(&barp, g_bar);
    cudaMemsetAsync(barp, 0, sizeof(unsigned));

    const int smemB = (1024 * 32 + 16 * 1024) * (int)sizeof(float);  // 196608
    cudaFuncSetAttribute(rnn_scan_kernel, cudaFuncAttributeMaxDynamicSharedMemorySize, smemB);

    // 1) input projection: grid (N/64, M/128) = (16, 256)
    input_proj_kernel<<<dim3(HID / BN, (TSQ * BATCH) / BM), 256>>>(x, Win, o_ip);

    // 2) persistent recurrent scan: 128 CTAs (co-resident: 1 CTA/SM, 128 < 148 SMs)
    rnn_scan_kernel<<<dim3(32, 4), 256, smemB>>>(o_ip, Wr, bias, o_hid);

    // 3) output projection + transpose: grid (256/64, 32768/128) = (4, 256)
    output_kernel<<<dim3(OUTD / BN, (TSQ * BATCH) / BM), 256>>>(Wout, o_out, o_outT);
}

// round 4
// speedup vs baseline: 1.6227x; 1.6227x over previous
#include <cuda_runtime.h>
#include <math.h>

// ---------------- problem constants ----------------
#define TSQ   512
#define BATCH 64
#define INP   256
#define HID   1024
#define OUTD  256
#define DT_A  0.05f

// output buffer layout (floats): [output_tensor | input_proj | tot_rnnhid | tot_output]
static const size_t O_OUTT = 0;                                  // (512,64,256)
static const size_t O_IP   = (size_t)TSQ * BATCH * OUTD;         // (64,512,1024)
static const size_t O_HID  = O_IP  + (size_t)BATCH * TSQ * HID;  // (64,512,1024)
static const size_t O_OUT  = O_HID + (size_t)BATCH * TSQ * HID;  // (64,512,256)

// ---------------- device scratch (static: no allocations allowed) ----------------
__device__ float    g_th2 [(size_t)TSQ * HID * BATCH];   // tanh(h): [t][k][b]  (GEMM A layout)
__device__ float    g_thbt[(size_t)BATCH * TSQ * HID];   // tanh(h): [b][t][k]  (output-GEMM layout)
__device__ float    g_part[2 * 128 * 4096];              // split-K partials, double-buffered by t parity
__device__ unsigned g_pflag[TSQ * 16];                   // partials-ready counters (per t, col-tile)
__device__ unsigned g_tflag[TSQ * 16];                   // th-ready counters (per t, col-tile)

// ---------------- f32x2 packed-FMA helpers (FFMA2: only reachable via PTX) ----------------
__device__ __forceinline__ unsigned long long pack2(float v) {
    unsigned long long r;
    asm("mov.b64 %0, {%1, %1};" : "=l"(r) : "r"(__float_as_uint(v)));
    return r;
}
__device__ __forceinline__ void fma2(unsigned long long& d, unsigned long long a, unsigned long long b) {
    asm("fma.rn.f32x2 %0, %1, %2, %0;" : "+l"(d) : "l"(a), "l"(b));
}
__device__ __forceinline__ float2 unpack2(unsigned long long v) {
    unsigned lo, hi;
    asm("mov.b64 {%0, %1}, %2;" : "=r"(lo), "=r"(hi) : "l"(v));
    return make_float2(__uint_as_float(lo), __uint_as_float(hi));
}

// =====================================================================
// Kernel A: input_proj[b][t][h] = sum_i x[t][b][i] * Win[i][h]
// GEMM M=32768, N=1024, K=256.  BM=128 BN=64 BK=16, 8x4/thread, FFMA2.
// =====================================================================
#define BM 128
#define BN 64
#define BK 16
#define AS_LD 136   // padded, keeps 16B alignment

__global__ __launch_bounds__(256) void input_proj_kernel(
    const float* __restrict__ x, const float* __restrict__ Win, float* __restrict__ ip)
{
    __shared__ float As[BK * AS_LD];
    __shared__ float Bs[BK * BN];

    const int tid = threadIdx.x;
    const int r0  = blockIdx.y * BM;
    const int c0  = blockIdx.x * BN;
    const int b   = r0 >> 9;
    const int t0  = r0 & 511;

    const int arow = tid >> 2;
    const int ac4  = tid & 3;
    const int brow = tid >> 4;
    const int bc4  = tid & 15;
    const int tx = tid & 15;
    const int ty = tid >> 4;

    unsigned long long acc[4][4];
#pragma unroll
    for (int i = 0; i < 4; i++)
#pragma unroll
        for (int j = 0; j < 4; j++) acc[i][j] = 0ull;

    for (int k0 = 0; k0 < INP; k0 += BK) {
#pragma unroll
        for (int p = 0; p < 2; p++) {
            const int row = arow + p * 64;
            const float4 v = *(const float4*)&x[((size_t)(t0 + row) * BATCH + b) * INP + k0 + ac4 * 4];
            As[(ac4 * 4 + 0) * AS_LD + row] = v.x;
            As[(ac4 * 4 + 1) * AS_LD + row] = v.y;
            As[(ac4 * 4 + 2) * AS_LD + row] = v.z;
            As[(ac4 * 4 + 3) * AS_LD + row] = v.w;
        }
        *(float4*)&Bs[brow * BN + bc4 * 4] =
            *(const float4*)&Win[(size_t)(k0 + brow) * HID + c0 + bc4 * 4];
        __syncthreads();

#pragma unroll
        for (int k = 0; k < BK; k++) {
            const ulonglong2 a01 = *(const ulonglong2*)&As[k * AS_LD + ty * 8];
            const ulonglong2 a23 = *(const ulonglong2*)&As[k * AS_LD + ty * 8 + 4];
            const float4 bf = *(const float4*)&Bs[k * BN + tx * 4];
            const unsigned long long b0 = pack2(bf.x), b1 = pack2(bf.y),
                                     b2 = pack2(bf.z), b3 = pack2(bf.w);
            fma2(acc[0][0], a01.x, b0); fma2(acc[0][1], a01.x, b1);
            fma2(acc[0][2], a01.x, b2); fma2(acc[0][3], a01.x, b3);
            fma2(acc[1][0], a01.y, b0); fma2(acc[1][1], a01.y, b1);
            fma2(acc[1][2], a01.y, b2); fma2(acc[1][3], a01.y, b3);
            fma2(acc[2][0], a23.x, b0); fma2(acc[2][1], a23.x, b1);
            fma2(acc[2][2], a23.x, b2); fma2(acc[2][3], a23.x, b3);
            fma2(acc[3][0], a23.y, b0); fma2(acc[3][1], a23.y, b1);
            fma2(acc[3][2], a23.y, b2); fma2(acc[3][3], a23.y, b3);
        }
        __syncthreads();
    }

#pragma unroll
    for (int rp = 0; rp < 4; rp++) {
        const int r = r0 + ty * 8 + 2 * rp;
        const float2 u0 = unpack2(acc[rp][0]), u1 = unpack2(acc[rp][1]);
        const float2 u2 = unpack2(acc[rp][2]), u3 = unpack2(acc[rp][3]);
        *(float4*)&ip[(size_t)r * HID + c0 + tx * 4]       = make_float4(u0.x, u1.x, u2.x, u3.x);
        *(float4*)&ip[(size_t)(r + 1) * HID + c0 + tx * 4] = make_float4(u0.y, u1.y, u2.y, u3.y);
    }
}

// =====================================================================
// Kernel B: persistent split-K recurrent scan, fine-grained flag sync.
// 128 CTAs: kc = bid>>4 (K-chunk of 128), ct = bid&15 (64-col tile).
// Persistent smem: Wr slice [128][64]. Per step: stage th slice, FFMA2 GEMM
// partial (64x64), store partials, flag; reduce own (8-row x 64-col) band,
// h update + tanh, store th in both layouts, flag.
// =====================================================================
__global__ __launch_bounds__(256) void rnn_scan_kernel(
    const float* __restrict__ ip, const float* __restrict__ Wr,
    const float* __restrict__ bias, float* __restrict__ hid)
{
    extern __shared__ float smem[];
    float* Ws = smem;           // [128][64] persistent Wr slice
    float* As = smem + 8192;    // [128][64] th slice for this step

    const int tid = threadIdx.x;
    const int bid = blockIdx.x;     // 0..127
    const int kc  = bid >> 4;       // 0..7
    const int ct  = bid & 15;       // 0..15

    // persistent Wr slice: Ws[k][c] = Wr[(kc*128+k)*1024 + ct*64 + c]
    for (int i = tid; i < 2048; i += 256) {
        const int k = i >> 4, c4 = i & 15;
        ((float4*)Ws)[k * 16 + c4] =
            __ldg((const float4*)&Wr[(size_t)(kc * 128 + k) * HID + ct * 64 + c4 * 4]);
    }

    // GEMM thread coords: 4 rows x 4 cols per thread
    const int tx = tid & 15;        // col group: cols 4tx..4tx+3
    const int ty = tid >> 4;        // row group: rows 4ty..4ty+3

    // reducer coords: (2 rows, 1 col) per thread over rows [8kc,+8) x cols [64ct,+64)
    const int lc  = tid & 63;
    const int rp  = tid >> 6;
    const int col = ct * 64 + lc;
    const int row = kc * 8 + rp * 2;
    const float bia = __ldg(&bias[col]);
    // partial-read float index for (row,col) within a producer's 4096-float block
    const int rfidx = ((lc & 3) * 1024) + ((row >> 2) * 16 + (lc >> 2)) * 4 + (row & 3);

    float h0 = 0.f, h1 = 0.f;
    volatile unsigned* pf = g_pflag;
    volatile unsigned* tf = g_tflag;

    __syncthreads();

    for (int t = 0; t < TSQ; t++) {
        if (t > 0) {
            // ---- wait for th col-tiles 2kc, 2kc+1 of step t-1 ----
            if (tid == 0) {
                while (tf[(t - 1) * 16 + 2 * kc]     < 8u) { }
                while (tf[(t - 1) * 16 + 2 * kc + 1] < 8u) { }
            }
            __syncthreads();
            __threadfence();

            // ---- stage th slice [t-1][kc*128..+128][0..63] (contiguous 32 KB) ----
            const float4* src = (const float4*)&g_th2[((size_t)(t - 1) * HID + kc * 128) * BATCH];
            float4* dst = (float4*)As;
#pragma unroll
            for (int i = 0; i < 8; i++)
                dst[tid + 256 * i] = __ldcg(&src[tid + 256 * i]);
            __syncthreads();

            // ---- FFMA2 GEMM: partial[64x64] over k-chunk of 128 ----
            unsigned long long acc[2][4];
#pragma unroll
            for (int i = 0; i < 2; i++)
#pragma unroll
                for (int j = 0; j < 4; j++) acc[i][j] = 0ull;

#pragma unroll 8
            for (int k = 0; k < 128; k++) {
                const ulonglong2 aa = ((const ulonglong2*)As)[k * 16 + ty]; // rows 4ty..4ty+3
                const float4 bv = ((const float4*)Ws)[k * 16 + tx];          // cols 4tx..4tx+3
                const unsigned long long b0 = pack2(bv.x), b1 = pack2(bv.y),
                                         b2 = pack2(bv.z), b3 = pack2(bv.w);
                fma2(acc[0][0], aa.x, b0); fma2(acc[0][1], aa.x, b1);
                fma2(acc[0][2], aa.x, b2); fma2(acc[0][3], aa.x, b3);
                fma2(acc[1][0], aa.y, b0); fma2(acc[1][1], aa.y, b1);
                fma2(acc[1][2], aa.y, b2); fma2(acc[1][3], aa.y, b3);
            }

            // ---- store partials (coalesced), double-buffered by parity ----
            float* gp = g_part + (size_t)(t & 1) * (128 * 4096) + (size_t)bid * 4096;
#pragma unroll
            for (int c = 0; c < 4; c++) {
                const float2 lo = unpack2(acc[0][c]);
                const float2 hi = unpack2(acc[1][c]);
                ((float4*)gp)[c * 256 + tid] = make_float4(lo.x, lo.y, hi.x, hi.y);
            }
            __threadfence();
            __syncthreads();
            if (tid == 0) atomicAdd((unsigned*)&g_pflag[t * 16 + ct], 1u);

            // ---- wait for all 8 K-chunk partials of this col-tile ----
            if (tid == 0) { while (pf[t * 16 + ct] < 8u) { } }
            __syncthreads();
            __threadfence();
        }

        // ---- reduction + state update for rows [8kc,+8) x cols [64ct,+64) ----
        float s0 = 0.f, s1 = 0.f;
        if (t > 0) {
            const float* gpb = g_part + (size_t)(t & 1) * (128 * 4096);
#pragma unroll
            for (int q = 0; q < 8; q++) {
                const float2 p = __ldcg((const float2*)&gpb[(size_t)(q * 16 + ct) * 4096 + rfidx]);
                s0 += p.x; s1 += p.y;
            }
        }
        const size_t i0 = ((size_t)row * TSQ + t) * HID + col;
        const size_t i1 = i0 + (size_t)TSQ * HID;
        const float ip0 = __ldg(&ip[i0]);
        const float ip1 = __ldg(&ip[i1]);
        h0 = (1.f - DT_A) * h0 + DT_A * (s0 + ip0 + bia);
        h1 = (1.f - DT_A) * h1 + DT_A * (s1 + ip1 + bia);
        hid[i0] = h0;
        hid[i1] = h1;
        const float th0 = tanhf(h0), th1 = tanhf(h1);
        g_thbt[i0] = th0;
        g_thbt[i1] = th1;
        *(float2*)&g_th2[((size_t)t * HID + col) * BATCH + row] = make_float2(th0, th1);

        __threadfence();
        __syncthreads();
        if (tid == 0) atomicAdd((unsigned*)&g_tflag[t * 16 + ct], 1u);
    }
}

// =====================================================================
// Kernel C: tot_output = tanh(hid) @ Wout  (tanh cached in g_thbt),
// plus transposed copy output_tensor[t][b][o].  FFMA2.
// =====================================================================
__global__ __launch_bounds__(256) void output_kernel(
    const float* __restrict__ Wout, float* __restrict__ tot_out, float* __restrict__ outT)
{
    __shared__ float As[BK * AS_LD];
    __shared__ float Bs[BK * BN];

    const int tid = threadIdx.x;
    const int r0  = blockIdx.y * BM;
    const int c0  = blockIdx.x * BN;

    const int arow = tid >> 2;
    const int ac4  = tid & 3;
    const int brow = tid >> 4;
    const int bc4  = tid & 15;
    const int tx = tid & 15;
    const int ty = tid >> 4;

    unsigned long long acc[4][4];
#pragma unroll
    for (int i = 0; i < 4; i++)
#pragma unroll
        for (int j = 0; j < 4; j++) acc[i][j] = 0ull;

    for (int k0 = 0; k0 < HID; k0 += BK) {
#pragma unroll
        for (int p = 0; p < 2; p++) {
            const int row = arow + p * 64;
            const float4 v = *(const float4*)&g_thbt[(size_t)(r0 + row) * HID + k0 + ac4 * 4];
            As[(ac4 * 4 + 0) * AS_LD + row] = v.x;
            As[(ac4 * 4 + 1) * AS_LD + row] = v.y;
            As[(ac4 * 4 + 2) * AS_LD + row] = v.z;
            As[(ac4 * 4 + 3) * AS_LD + row] = v.w;
        }
        *(float4*)&Bs[brow * BN + bc4 * 4] =
            *(const float4*)&Wout[(size_t)(k0 + brow) * OUTD + c0 + bc4 * 4];
        __syncthreads();

#pragma unroll
        for (int k = 0; k < BK; k++) {
            const ulonglong2 a01 = *(const ulonglong2*)&As[k * AS_LD + ty * 8];
            const ulonglong2 a23 = *(const ulonglong2*)&As[k * AS_LD + ty * 8 + 4];
            const float4 bf = *(const float4*)&Bs[k * BN + tx * 4];
            const unsigned long long b0 = pack2(bf.x), b1 = pack2(bf.y),
                                     b2 = pack2(bf.z), b3 = pack2(bf.w);
            fma2(acc[0][0], a01.x, b0); fma2(acc[0][1], a01.x, b1);
            fma2(acc[0][2], a01.x, b2); fma2(acc[0][3], a01.x, b3);
            fma2(acc[1][0], a01.y, b0); fma2(acc[1][1], a01.y, b1);
            fma2(acc[1][2], a01.y, b2); fma2(acc[1][3], a01.y, b3);
            fma2(acc[2][0], a23.x, b0); fma2(acc[2][1], a23.x, b1);
            fma2(acc[2][2], a23.x, b2); fma2(acc[2][3], a23.x, b3);
            fma2(acc[3][0], a23.y, b0); fma2(acc[3][1], a23.y, b1);
            fma2(acc[3][2], a23.y, b2); fma2(acc[3][3], a23.y, b3);
        }
        __syncthreads();
    }

#pragma unroll
    for (int rp = 0; rp < 4; rp++) {
        const int r  = r0 + ty * 8 + 2 * rp;
        const float2 u0 = unpack2(acc[rp][0]), u1 = unpack2(acc[rp][1]);
        const float2 u2 = unpack2(acc[rp][2]), u3 = unpack2(acc[rp][3]);
        const float4 v0 = make_float4(u0.x, u1.x, u2.x, u3.x);
        const float4 v1 = make_float4(u0.y, u1.y, u2.y, u3.y);
        const int b0i = r >> 9,        t0i = r & 511;
        const int b1i = (r + 1) >> 9,  t1i = (r + 1) & 511;
        *(float4*)&tot_out[(size_t)r * OUTD + c0 + tx * 4]       = v0;
        *(float4*)&tot_out[(size_t)(r + 1) * OUTD + c0 + tx * 4] = v1;
        *(float4*)&outT[((size_t)t0i * BATCH + b0i) * OUTD + c0 + tx * 4] = v0;
        *(float4*)&outT[((size_t)t1i * BATCH + b1i) * OUTD + c0 + tx * 4] = v1;
    }
}

// =====================================================================
// launch
// =====================================================================
extern "C" void kernel_launch(void* const* d_in, const int* in_sizes, int n_in,
                              void* d_out, int out_size)
{
    const float* x    = (const float*)d_in[0];
    const float* Win  = (const float*)d_in[1];
    const float* Wr   = (const float*)d_in[2];
    const float* bias = (const float*)d_in[3];
    const float* Wout = (const float*)d_in[4];

    float* out    = (float*)d_out;
    float* o_outT = out + O_OUTT;
    float* o_ip   = out + O_IP;
    float* o_hid  = out + O_HID;
    float* o_out  = out + O_OUT;

    // reset flag counters each launch (graph-capturable, deterministic replays)
    void* p0 = nullptr; void* p1 = nullptr;
    cudaGetSymbolAddress(&p0, g_pflag);
    cudaGetSymbolAddress(&p1, g_tflag);
    cudaMemsetAsync(p0, 0, TSQ * 16 * sizeof(unsigned));
    cudaMemsetAsync(p1, 0, TSQ * 16 * sizeof(unsigned));

    const int smemB = 2 * 128 * 64 * (int)sizeof(float);  // 65536
    cudaFuncSetAttribute(rnn_scan_kernel, cudaFuncAttributeMaxDynamicSharedMemorySize, smemB);

    // 1) input projection
    input_proj_kernel<<<dim3(HID / BN, (TSQ * BATCH) / BM), 256>>>(x, Win, o_ip);

    // 2) persistent split-K recurrent scan: 128 CTAs (all resident in wave 1)
    rnn_scan_kernel<<<128, 256, smemB>>>(o_ip, Wr, bias, o_hid);

    // 3) output projection + transpose
    output_kernel<<<dim3(OUTD / BN, (TSQ * BATCH) / BM), 256>>>(Wout, o_out, o_outT);
}

// round 5
// speedup vs baseline: 1.6941x; 1.0440x over previous
#include <cuda_runtime.h>
#include <math.h>

// ---------------- problem constants ----------------
#define TSQ   512
#define BATCH 64
#define INP   256
#define HID   1024
#define OUTD  256
#define DT_A  0.05f

// output buffer layout (floats): [output_tensor | input_proj | tot_rnnhid | tot_output]
static const size_t O_OUTT = 0;                                  // (512,64,256)
static const size_t O_IP   = (size_t)TSQ * BATCH * OUTD;         // (64,512,1024)
static const size_t O_HID  = O_IP  + (size_t)BATCH * TSQ * HID;  // (64,512,1024)
static const size_t O_OUT  = O_HID + (size_t)BATCH * TSQ * HID;  // (64,512,256)

// flag padding: one counter per 128-byte L2 line to avoid LTS serialization
#define FPAD 32

// ---------------- device scratch (static: no allocations allowed) ----------------
__device__ float    g_th2 [(size_t)TSQ * HID * BATCH];   // tanh(h): [t][k][b]  (GEMM A layout)
__device__ float    g_thbt[(size_t)BATCH * TSQ * HID];   // tanh(h): [b][t][k]  (output-GEMM layout)
__device__ float    g_part[2 * 128 * 4096];              // split-K partials, double-buffered by t parity
__device__ unsigned g_pflag[TSQ * 16 * FPAD];            // partials-ready counters (per t, col-tile)
__device__ unsigned g_tflag[TSQ * 16 * FPAD];            // th-ready counters (per t, col-tile)

// ---------------- f32x2 packed-FMA helpers (FFMA2: only reachable via PTX) ----------------
__device__ __forceinline__ unsigned long long pack2(float v) {
    unsigned long long r;
    asm("mov.b64 %0, {%1, %1};" : "=l"(r) : "r"(__float_as_uint(v)));
    return r;
}
__device__ __forceinline__ void fma2(unsigned long long& d, unsigned long long a, unsigned long long b) {
    asm("fma.rn.f32x2 %0, %1, %2, %0;" : "+l"(d) : "l"(a), "l"(b));
}
__device__ __forceinline__ float2 unpack2(unsigned long long v) {
    unsigned lo, hi;
    asm("mov.b64 {%0, %1}, %2;" : "=r"(lo), "=r"(hi) : "l"(v));
    return make_float2(__uint_as_float(lo), __uint_as_float(hi));
}

// ---------------- acquire-load / release-arrive sync helpers ----------------
__device__ __forceinline__ unsigned ld_acq(const unsigned* p) {
    unsigned v;
    asm volatile("ld.acquire.gpu.global.u32 %0, [%1];" : "=r"(v) : "l"(p) : "memory");
    return v;
}
__device__ __forceinline__ void red_rel_add(unsigned* p, unsigned v) {
    asm volatile("red.release.gpu.global.add.u32 [%0], %1;" :: "l"(p), "r"(v) : "memory");
}

// =====================================================================
// Kernel A: input_proj[b][t][h] = sum_i x[t][b][i] * Win[i][h]
// GEMM M=32768, N=1024, K=256.  BM=128 BN=64 BK=16, 8x4/thread, FFMA2.
// =====================================================================
#define BM 128
#define BN 64
#define BK 16
#define AS_LD 136   // padded, keeps 16B alignment

__global__ __launch_bounds__(256) void input_proj_kernel(
    const float* __restrict__ x, const float* __restrict__ Win, float* __restrict__ ip)
{
    __shared__ float As[BK * AS_LD];
    __shared__ float Bs[BK * BN];

    const int tid = threadIdx.x;
    const int r0  = blockIdx.y * BM;
    const int c0  = blockIdx.x * BN;
    const int b   = r0 >> 9;
    const int t0  = r0 & 511;

    const int arow = tid >> 2;
    const int ac4  = tid & 3;
    const int brow = tid >> 4;
    const int bc4  = tid & 15;
    const int tx = tid & 15;
    const int ty = tid >> 4;

    unsigned long long acc[4][4];
#pragma unroll
    for (int i = 0; i < 4; i++)
#pragma unroll
        for (int j = 0; j < 4; j++) acc[i][j] = 0ull;

    for (int k0 = 0; k0 < INP; k0 += BK) {
#pragma unroll
        for (int p = 0; p < 2; p++) {
            const int row = arow + p * 64;
            const float4 v = *(const float4*)&x[((size_t)(t0 + row) * BATCH + b) * INP + k0 + ac4 * 4];
            As[(ac4 * 4 + 0) * AS_LD + row] = v.x;
            As[(ac4 * 4 + 1) * AS_LD + row] = v.y;
            As[(ac4 * 4 + 2) * AS_LD + row] = v.z;
            As[(ac4 * 4 + 3) * AS_LD + row] = v.w;
        }
        *(float4*)&Bs[brow * BN + bc4 * 4] =
            *(const float4*)&Win[(size_t)(k0 + brow) * HID + c0 + bc4 * 4];
        __syncthreads();

#pragma unroll
        for (int k = 0; k < BK; k++) {
            const ulonglong2 a01 = *(const ulonglong2*)&As[k * AS_LD + ty * 8];
            const ulonglong2 a23 = *(const ulonglong2*)&As[k * AS_LD + ty * 8 + 4];
            const float4 bf = *(const float4*)&Bs[k * BN + tx * 4];
            const unsigned long long b0 = pack2(bf.x), b1 = pack2(bf.y),
                                     b2 = pack2(bf.z), b3 = pack2(bf.w);
            fma2(acc[0][0], a01.x, b0); fma2(acc[0][1], a01.x, b1);
            fma2(acc[0][2], a01.x, b2); fma2(acc[0][3], a01.x, b3);
            fma2(acc[1][0], a01.y, b0); fma2(acc[1][1], a01.y, b1);
            fma2(acc[1][2], a01.y, b2); fma2(acc[1][3], a01.y, b3);
            fma2(acc[2][0], a23.x, b0); fma2(acc[2][1], a23.x, b1);
            fma2(acc[2][2], a23.x, b2); fma2(acc[2][3], a23.x, b3);
            fma2(acc[3][0], a23.y, b0); fma2(acc[3][1], a23.y, b1);
            fma2(acc[3][2], a23.y, b2); fma2(acc[3][3], a23.y, b3);
        }
        __syncthreads();
    }

#pragma unroll
    for (int rp = 0; rp < 4; rp++) {
        const int r = r0 + ty * 8 + 2 * rp;
        const float2 u0 = unpack2(acc[rp][0]), u1 = unpack2(acc[rp][1]);
        const float2 u2 = unpack2(acc[rp][2]), u3 = unpack2(acc[rp][3]);
        *(float4*)&ip[(size_t)r * HID + c0 + tx * 4]       = make_float4(u0.x, u1.x, u2.x, u3.x);
        *(float4*)&ip[(size_t)(r + 1) * HID + c0 + tx * 4] = make_float4(u0.y, u1.y, u2.y, u3.y);
    }
}

// =====================================================================
// Kernel B: persistent split-K recurrent scan, fine-grained flag sync.
// 128 CTAs: kc = bid>>4 (K-chunk of 128), ct = bid&15 (64-col tile).
// Sync: padded per-(t,tile) counters; consumers use all-thread
// ld.acquire.gpu spins (no tid0 spin, no consumer-side bar/fence);
// producers use per-thread fence + bar + tid0 release-red.
// =====================================================================
__global__ __launch_bounds__(256) void rnn_scan_kernel(
    const float* __restrict__ ip, const float* __restrict__ Wr,
    const float* __restrict__ bias, float* __restrict__ hid)
{
    extern __shared__ float smem[];
    float* Ws = smem;           // [128][64] persistent Wr slice
    float* As = smem + 8192;    // [128][64] th slice for this step

    const int tid = threadIdx.x;
    const int bid = blockIdx.x;     // 0..127
    const int kc  = bid >> 4;       // 0..7
    const int ct  = bid & 15;       // 0..15

    // persistent Wr slice: Ws[k][c] = Wr[(kc*128+k)*1024 + ct*64 + c]
    for (int i = tid; i < 2048; i += 256) {
        const int k = i >> 4, c4 = i & 15;
        ((float4*)Ws)[k * 16 + c4] =
            __ldg((const float4*)&Wr[(size_t)(kc * 128 + k) * HID + ct * 64 + c4 * 4]);
    }

    // GEMM thread coords: 4 rows x 4 cols per thread
    const int tx = tid & 15;
    const int ty = tid >> 4;

    // reducer coords: (2 rows, 1 col) per thread over rows [8kc,+8) x cols [64ct,+64)
    const int lc  = tid & 63;
    const int rp  = tid >> 6;
    const int col = ct * 64 + lc;
    const int row = kc * 8 + rp * 2;
    const float bia = __ldg(&bias[col]);
    const int rfidx = ((lc & 3) * 1024) + ((row >> 2) * 16 + (lc >> 2)) * 4 + (row & 3);

    float h0 = 0.f, h1 = 0.f;

    __syncthreads();

    for (int t = 0; t < TSQ; t++) {
        // prefetch ip for this step (independent of t-1 data)
        const size_t i0 = ((size_t)row * TSQ + t) * HID + col;
        const size_t i1 = i0 + (size_t)TSQ * HID;
        const float ip0 = __ldg(&ip[i0]);
        const float ip1 = __ldg(&ip[i1]);

        float s0 = 0.f, s1 = 0.f;
        if (t > 0) {
            // ---- all-thread acquire spin: th col-tiles 2kc, 2kc+1 of step t-1 ----
            const unsigned* f0 = &g_tflag[(size_t)((t - 1) * 16 + 2 * kc) * FPAD];
            const unsigned* f1 = f0 + FPAD;
            while (ld_acq(f0) < 8u) { }
            while (ld_acq(f1) < 8u) { }

            // ---- stage th slice [t-1][kc*128..+128][0..63] (contiguous 32 KB) ----
            const float4* src = (const float4*)&g_th2[((size_t)(t - 1) * HID + kc * 128) * BATCH];
            float4* dst = (float4*)As;
#pragma unroll
            for (int i = 0; i < 8; i++)
                dst[tid + 256 * i] = __ldcg(&src[tid + 256 * i]);
            __syncthreads();

            // ---- FFMA2 GEMM: partial[64x64] over k-chunk of 128 ----
            unsigned long long acc[2][4];
#pragma unroll
            for (int i = 0; i < 2; i++)
#pragma unroll
                for (int j = 0; j < 4; j++) acc[i][j] = 0ull;

#pragma unroll 8
            for (int k = 0; k < 128; k++) {
                const ulonglong2 aa = ((const ulonglong2*)As)[k * 16 + ty];
                const float4 bv = ((const float4*)Ws)[k * 16 + tx];
                const unsigned long long b0 = pack2(bv.x), b1 = pack2(bv.y),
                                         b2 = pack2(bv.z), b3 = pack2(bv.w);
                fma2(acc[0][0], aa.x, b0); fma2(acc[0][1], aa.x, b1);
                fma2(acc[0][2], aa.x, b2); fma2(acc[0][3], aa.x, b3);
                fma2(acc[1][0], aa.y, b0); fma2(acc[1][1], aa.y, b1);
                fma2(acc[1][2], aa.y, b2); fma2(acc[1][3], aa.y, b3);
            }

            // ---- store partials (coalesced), double-buffered by parity ----
            float* gp = g_part + (size_t)(t & 1) * (128 * 4096) + (size_t)bid * 4096;
#pragma unroll
            for (int c = 0; c < 4; c++) {
                const float2 lo = unpack2(acc[0][c]);
                const float2 hi = unpack2(acc[1][c]);
                ((float4*)gp)[c * 256 + tid] = make_float4(lo.x, lo.y, hi.x, hi.y);
            }
            __threadfence();
            __syncthreads();
            if (tid == 0) red_rel_add(&g_pflag[(size_t)(t * 16 + ct) * FPAD], 1u);

            // ---- all-thread acquire spin: all 8 K-chunk partials of this col-tile ----
            const unsigned* fp = &g_pflag[(size_t)(t * 16 + ct) * FPAD];
            while (ld_acq(fp) < 8u) { }

            // ---- reduce (L2-fresh reads) ----
            const float* gpb = g_part + (size_t)(t & 1) * (128 * 4096);
#pragma unroll
            for (int q = 0; q < 8; q++) {
                const float2 p = __ldcg((const float2*)&gpb[(size_t)(q * 16 + ct) * 4096 + rfidx]);
                s0 += p.x; s1 += p.y;
            }
        }

        // ---- state update for rows (row,row+1) x col ----
        h0 = (1.f - DT_A) * h0 + DT_A * (s0 + ip0 + bia);
        h1 = (1.f - DT_A) * h1 + DT_A * (s1 + ip1 + bia);
        hid[i0] = h0;
        hid[i1] = h1;
        const float th0 = tanhf(h0), th1 = tanhf(h1);
        g_thbt[i0] = th0;
        g_thbt[i1] = th1;
        *(float2*)&g_th2[((size_t)t * HID + col) * BATCH + row] = make_float2(th0, th1);

        __threadfence();
        __syncthreads();
        if (tid == 0) red_rel_add(&g_tflag[(size_t)(t * 16 + ct) * FPAD], 1u);
    }
}

// =====================================================================
// Kernel C: tot_output = tanh(hid) @ Wout  (tanh cached in g_thbt),
// plus transposed copy output_tensor[t][b][o].  FFMA2.
// =====================================================================
__global__ __launch_bounds__(256) void output_kernel(
    const float* __restrict__ Wout, float* __restrict__ tot_out, float* __restrict__ outT)
{
    __shared__ float As[BK * AS_LD];
    __shared__ float Bs[BK * BN];

    const int tid = threadIdx.x;
    const int r0  = blockIdx.y * BM;
    const int c0  = blockIdx.x * BN;

    const int arow = tid >> 2;
    const int ac4  = tid & 3;
    const int brow = tid >> 4;
    const int bc4  = tid & 15;
    const int tx = tid & 15;
    const int ty = tid >> 4;

    unsigned long long acc[4][4];
#pragma unroll
    for (int i = 0; i < 4; i++)
#pragma unroll
        for (int j = 0; j < 4; j++) acc[i][j] = 0ull;

    for (int k0 = 0; k0 < HID; k0 += BK) {
#pragma unroll
        for (int p = 0; p < 2; p++) {
            const int row = arow + p * 64;
            const float4 v = *(const float4*)&g_thbt[(size_t)(r0 + row) * HID + k0 + ac4 * 4];
            As[(ac4 * 4 + 0) * AS_LD + row] = v.x;
            As[(ac4 * 4 + 1) * AS_LD + row] = v.y;
            As[(ac4 * 4 + 2) * AS_LD + row] = v.z;
            As[(ac4 * 4 + 3) * AS_LD + row] = v.w;
        }
        *(float4*)&Bs[brow * BN + bc4 * 4] =
            *(const float4*)&Wout[(size_t)(k0 + brow) * OUTD + c0 + bc4 * 4];
        __syncthreads();

#pragma unroll
        for (int k = 0; k < BK; k++) {
            const ulonglong2 a01 = *(const ulonglong2*)&As[k * AS_LD + ty * 8];
            const ulonglong2 a23 = *(const ulonglong2*)&As[k * AS_LD + ty * 8 + 4];
            const float4 bf = *(const float4*)&Bs[k * BN + tx * 4];
            const unsigned long long b0 = pack2(bf.x), b1 = pack2(bf.y),
                                     b2 = pack2(bf.z), b3 = pack2(bf.w);
            fma2(acc[0][0], a01.x, b0); fma2(acc[0][1], a01.x, b1);
            fma2(acc[0][2], a01.x, b2); fma2(acc[0][3], a01.x, b3);
            fma2(acc[1][0], a01.y, b0); fma2(acc[1][1], a01.y, b1);
            fma2(acc[1][2], a01.y, b2); fma2(acc[1][3], a01.y, b3);
            fma2(acc[2][0], a23.x, b0); fma2(acc[2][1], a23.x, b1);
            fma2(acc[2][2], a23.x, b2); fma2(acc[2][3], a23.x, b3);
            fma2(acc[3][0], a23.y, b0); fma2(acc[3][1], a23.y, b1);
            fma2(acc[3][2], a23.y, b2); fma2(acc[3][3], a23.y, b3);
        }
        __syncthreads();
    }

#pragma unroll
    for (int rp = 0; rp < 4; rp++) {
        const int r  = r0 + ty * 8 + 2 * rp;
        const float2 u0 = unpack2(acc[rp][0]), u1 = unpack2(acc[rp][1]);
        const float2 u2 = unpack2(acc[rp][2]), u3 = unpack2(acc[rp][3]);
        const float4 v0 = make_float4(u0.x, u1.x, u2.x, u3.x);
        const float4 v1 = make_float4(u0.y, u1.y, u2.y, u3.y);
        const int b0i = r >> 9,        t0i = r & 511;
        const int b1i = (r + 1) >> 9,  t1i = (r + 1) & 511;
        *(float4*)&tot_out[(size_t)r * OUTD + c0 + tx * 4]       = v0;
        *(float4*)&tot_out[(size_t)(r + 1) * OUTD + c0 + tx * 4] = v1;
        *(float4*)&outT[((size_t)t0i * BATCH + b0i) * OUTD + c0 + tx * 4] = v0;
        *(float4*)&outT[((size_t)t1i * BATCH + b1i) * OUTD + c0 + tx * 4] = v1;
    }
}

// =====================================================================
// launch
// =====================================================================
extern "C" void kernel_launch(void* const* d_in, const int* in_sizes, int n_in,
                              void* d_out, int out_size)
{
    const float* x    = (const float*)d_in[0];
    const float* Win  = (const float*)d_in[1];
    const float* Wr   = (const float*)d_in[2];
    const float* bias = (const float*)d_in[3];
    const float* Wout = (const float*)d_in[4];

    float* out    = (float*)d_out;
    float* o_outT = out + O_OUTT;
    float* o_ip   = out + O_IP;
    float* o_hid  = out + O_HID;
    float* o_out  = out + O_OUT;

    // reset flag counters each launch (graph-capturable, deterministic replays)
    void* p0 = nullptr; void* p1 = nullptr;
    cudaGetSymbolAddress(&p0, g_pflag);
    cudaGetSymbolAddress(&p1, g_tflag);
    cudaMemsetAsync(p0, 0, (size_t)TSQ * 16 * FPAD * sizeof(unsigned));
    cudaMemsetAsync(p1, 0, (size_t)TSQ * 16 * FPAD * sizeof(unsigned));

    const int smemB = 2 * 128 * 64 * (int)sizeof(float);  // 65536
    cudaFuncSetAttribute(rnn_scan_kernel, cudaFuncAttributeMaxDynamicSharedMemorySize, smemB);

    // 1) input projection
    input_proj_kernel<<<dim3(HID / BN, (TSQ * BATCH) / BM), 256>>>(x, Win, o_ip);

    // 2) persistent split-K recurrent scan: 128 CTAs (all resident in wave 1)
    rnn_scan_kernel<<<128, 256, smemB>>>(o_ip, Wr, bias, o_hid);

    // 3) output projection + transpose
    output_kernel<<<dim3(OUTD / BN, (TSQ * BATCH) / BM), 256>>>(Wout, o_out, o_outT);
}